// round 1
// baseline (speedup 1.0000x reference)
#include <cuda_runtime.h>
#include <cstdint>

namespace {
constexpr int Bn = 16, Cn = 128, Tn = 128, Hn = 128;
constexpr int BC = Bn * Cn;
}

// Scratch (no cudaMalloc allowed): 5 MB total
__device__ float g_Ut[BC * Hn];     // clone @ W_thorn[:H] + b_thorn
__device__ float g_Uc[BC * Hn];     // clone @ W_clone[:H] + b_clone
__device__ float g_Vc[BC * Hn];     // clone @ W_clone[H:2H]
__device__ float g_thorn[BC * Hn];  // thorn_agg
__device__ float g_cagg[BC * Hn];   // clone_agg

// ---------------------------------------------------------------------------
// Precompute: out(2048x128) = clone(2048x128) @ Wsub(128x128) [+ bias]
// grid.x = 128 (16-row tiles), grid.y = 3 (which product)
// ---------------------------------------------------------------------------
__global__ __launch_bounds__(256) void precompute_kernel(
    const float* __restrict__ clone,
    const float* __restrict__ W_thorn, const float* __restrict__ b_thorn,
    const float* __restrict__ W_clone, const float* __restrict__ b_clone)
{
    const float* W;
    const float* bias;
    float* out;
    if (blockIdx.y == 0)      { W = W_thorn;         bias = b_thorn; out = g_Ut; }
    else if (blockIdx.y == 1) { W = W_clone;         bias = b_clone; out = g_Uc; }
    else                      { W = W_clone + Hn*Hn; bias = nullptr; out = g_Vc; }

    __shared__ float sA[16][32];
    __shared__ float sW[32][128];

    const int tid = threadIdx.x;
    const int tx = tid & 31;   // col group: cols tx*4 .. tx*4+3
    const int ty = tid >> 5;   // row group: rows ty*2, ty*2+1
    const int m0 = blockIdx.x * 16;

    float acc[2][4];
    #pragma unroll
    for (int r = 0; r < 2; r++)
        #pragma unroll
        for (int j = 0; j < 4; j++) acc[r][j] = 0.f;

    for (int k0 = 0; k0 < Hn; k0 += 32) {
        {   // A tile 16x32 (float2 per thread)
            int r  = tid >> 4;
            int kc = (tid & 15) * 2;
            float2 v = *reinterpret_cast<const float2*>(
                clone + (size_t)(m0 + r) * Hn + k0 + kc);
            sA[r][kc] = v.x; sA[r][kc + 1] = v.y;
        }
        #pragma unroll
        for (int i = 0; i < 4; i++) {  // W tile 32x128 (4 x float4 per thread)
            int f  = tid + 256 * i;
            int kk = f >> 5;
            int n  = (f & 31) * 4;
            float4 v = *reinterpret_cast<const float4*>(
                W + (size_t)(k0 + kk) * Hn + n);
            *reinterpret_cast<float4*>(&sW[kk][n]) = v;
        }
        __syncthreads();
        #pragma unroll
        for (int kk = 0; kk < 32; kk++) {
            float a0 = sA[ty * 2][kk];
            float a1 = sA[ty * 2 + 1][kk];
            float4 w = *reinterpret_cast<const float4*>(&sW[kk][tx * 4]);
            acc[0][0] = fmaf(a0, w.x, acc[0][0]);
            acc[0][1] = fmaf(a0, w.y, acc[0][1]);
            acc[0][2] = fmaf(a0, w.z, acc[0][2]);
            acc[0][3] = fmaf(a0, w.w, acc[0][3]);
            acc[1][0] = fmaf(a1, w.x, acc[1][0]);
            acc[1][1] = fmaf(a1, w.y, acc[1][1]);
            acc[1][2] = fmaf(a1, w.z, acc[1][2]);
            acc[1][3] = fmaf(a1, w.w, acc[1][3]);
        }
        __syncthreads();
    }

    float b0 = 0.f, b1 = 0.f, b2 = 0.f, b3 = 0.f;
    if (bias) {
        float4 bb = *reinterpret_cast<const float4*>(bias + tx * 4);
        b0 = bb.x; b1 = bb.y; b2 = bb.z; b3 = bb.w;
    }
    #pragma unroll
    for (int r = 0; r < 2; r++) {
        int row = m0 + ty * 2 + r;
        float4 o;
        o.x = acc[r][0] + b0; o.y = acc[r][1] + b1;
        o.z = acc[r][2] + b2; o.w = acc[r][3] + b3;
        *reinterpret_cast<float4*>(&out[(size_t)row * Hn + tx * 4]) = o;
    }
}

// ---------------------------------------------------------------------------
// Branch kernel: one CTA per (b,c). Y = Rel(128x128) @ W3(128x128),
// epilogue adds u (+ per-row v for clone branch), mask*relu, max over rows.
// ---------------------------------------------------------------------------
template <bool CLONE>
__global__ __launch_bounds__(256, 2) void branch_kernel(
    const float* __restrict__ rel,   // (B, C, 128, H)
    const float* __restrict__ W3,    // (H, H) row-major
    const int*   __restrict__ mask)  // (B, 128)
{
    __shared__ float sA[128][20];    // rel tile [j][k], padded
    __shared__ float sB[16][128];    // W tile  [k][n]

    const int tid = threadIdx.x;
    const int tx = tid & 15;   // cols: tx*4..+3 and 64+tx*4..+3
    const int ty = tid >> 4;   // rows: ty*4..+3 and 64+ty*4..+3
    const int bc = blockIdx.x;
    const int b  = bc >> 7;

    const float* A = rel + (size_t)bc * (Tn * Hn);

    float acc[8][8];
    #pragma unroll
    for (int i = 0; i < 8; i++)
        #pragma unroll
        for (int j = 0; j < 8; j++) acc[i][j] = 0.f;

    for (int k0 = 0; k0 < Hn; k0 += 16) {
        #pragma unroll
        for (int i = 0; i < 2; i++) {  // A tile: 128x16, float4 per thread x2
            int f  = tid + 256 * i;
            int j  = f >> 2;
            int kc = (f & 3) << 2;
            float4 v = *reinterpret_cast<const float4*>(A + (size_t)j * Hn + k0 + kc);
            *reinterpret_cast<float4*>(&sA[j][kc]) = v;
        }
        #pragma unroll
        for (int i = 0; i < 2; i++) {  // W tile: 16x128
            int f  = tid + 256 * i;
            int kk = f >> 5;
            int n  = (f & 31) << 2;
            float4 v = *reinterpret_cast<const float4*>(
                W3 + (size_t)(k0 + kk) * Hn + n);
            *reinterpret_cast<float4*>(&sB[kk][n]) = v;
        }
        __syncthreads();
        #pragma unroll
        for (int kk = 0; kk < 16; kk++) {
            float a[8], bb[8];
            #pragma unroll
            for (int i = 0; i < 4; i++) {
                a[i]     = sA[ty * 4 + i][kk];
                a[4 + i] = sA[64 + ty * 4 + i][kk];
            }
            float4 w0 = *reinterpret_cast<const float4*>(&sB[kk][tx * 4]);
            float4 w1 = *reinterpret_cast<const float4*>(&sB[kk][64 + tx * 4]);
            bb[0] = w0.x; bb[1] = w0.y; bb[2] = w0.z; bb[3] = w0.w;
            bb[4] = w1.x; bb[5] = w1.y; bb[6] = w1.z; bb[7] = w1.w;
            #pragma unroll
            for (int i = 0; i < 8; i++)
                #pragma unroll
                for (int j = 0; j < 8; j++)
                    acc[i][j] = fmaf(a[i], bb[j], acc[i][j]);
        }
        __syncthreads();
    }

    // ---- fused epilogue: add u (and v), mask*relu, column-wise max ----
    const float* U = CLONE ? g_Uc : g_Ut;
    float u[8];
    {
        float4 u0 = *reinterpret_cast<const float4*>(U + (size_t)bc * Hn + tx * 4);
        float4 u1 = *reinterpret_cast<const float4*>(U + (size_t)bc * Hn + 64 + tx * 4);
        u[0] = u0.x; u[1] = u0.y; u[2] = u0.z; u[3] = u0.w;
        u[4] = u1.x; u[5] = u1.y; u[6] = u1.z; u[7] = u1.w;
    }

    float cmax[8];
    #pragma unroll
    for (int j = 0; j < 8; j++) cmax[j] = 0.f;

    #pragma unroll
    for (int i = 0; i < 8; i++) {
        int row = (i < 4) ? (ty * 4 + i) : (64 + ty * 4 + (i - 4));
        if (mask[b * 128 + row]) {
            if (CLONE) {
                const float* vr = g_Vc + (size_t)(b * Cn + row) * Hn;
                float4 v0 = *reinterpret_cast<const float4*>(vr + tx * 4);
                float4 v1 = *reinterpret_cast<const float4*>(vr + 64 + tx * 4);
                float vv[8] = {v0.x, v0.y, v0.z, v0.w, v1.x, v1.y, v1.z, v1.w};
                #pragma unroll
                for (int j = 0; j < 8; j++) {
                    float val = acc[i][j] + u[j] + vv[j];
                    cmax[j] = fmaxf(cmax[j], fmaxf(val, 0.f));
                }
            } else {
                #pragma unroll
                for (int j = 0; j < 8; j++) {
                    float val = acc[i][j] + u[j];
                    cmax[j] = fmaxf(cmax[j], fmaxf(val, 0.f));
                }
            }
        }
    }

    __syncthreads();  // done reading sA; reuse as reduction scratch
    float (*red)[128] = reinterpret_cast<float(*)[128]>(&sA[0][0]);
    #pragma unroll
    for (int j = 0; j < 8; j++) {
        int col = (j < 4) ? (tx * 4 + j) : (64 + tx * 4 + (j - 4));
        red[ty][col] = cmax[j];
    }
    __syncthreads();
    if (tid < 128) {
        float m = 0.f;
        #pragma unroll
        for (int r = 0; r < 16; r++) m = fmaxf(m, red[r][tid]);
        float* out = CLONE ? g_cagg : g_thorn;
        out[(size_t)bc * Hn + tid] = m;
    }
}

// ---------------------------------------------------------------------------
// Final: out = clone + relu(concat(clone,food,thorn_agg,clone_agg) @ W_agg + b)
// grid.x = 128 (16-row tiles), K = 512 assembled on the fly
// ---------------------------------------------------------------------------
__global__ __launch_bounds__(256) void final_kernel(
    const float* __restrict__ clone,
    const float* __restrict__ food,
    const float* __restrict__ W_agg,   // (512, 128)
    const float* __restrict__ b_agg,
    float* __restrict__ out)
{
    __shared__ float sA[16][32];
    __shared__ float sW[32][128];

    const int tid = threadIdx.x;
    const int tx = tid & 31;
    const int ty = tid >> 5;
    const int m0 = blockIdx.x * 16;

    float acc[2][4];
    #pragma unroll
    for (int r = 0; r < 2; r++)
        #pragma unroll
        for (int j = 0; j < 4; j++) acc[r][j] = 0.f;

    for (int k0 = 0; k0 < 4 * Hn; k0 += 32) {
        const float* src;
        int s = k0 >> 7;
        if (s == 0)      src = clone;
        else if (s == 1) src = food;
        else if (s == 2) src = g_thorn;
        else             src = g_cagg;
        int kc0 = k0 & 127;
        {
            int r  = tid >> 4;
            int kc = (tid & 15) * 2;
            float2 v = *reinterpret_cast<const float2*>(
                src + (size_t)(m0 + r) * Hn + kc0 + kc);
            sA[r][kc] = v.x; sA[r][kc + 1] = v.y;
        }
        #pragma unroll
        for (int i = 0; i < 4; i++) {
            int f  = tid + 256 * i;
            int kk = f >> 5;
            int n  = (f & 31) * 4;
            float4 v = *reinterpret_cast<const float4*>(
                W_agg + (size_t)(k0 + kk) * Hn + n);
            *reinterpret_cast<float4*>(&sW[kk][n]) = v;
        }
        __syncthreads();
        #pragma unroll
        for (int kk = 0; kk < 32; kk++) {
            float a0 = sA[ty * 2][kk];
            float a1 = sA[ty * 2 + 1][kk];
            float4 w = *reinterpret_cast<const float4*>(&sW[kk][tx * 4]);
            acc[0][0] = fmaf(a0, w.x, acc[0][0]);
            acc[0][1] = fmaf(a0, w.y, acc[0][1]);
            acc[0][2] = fmaf(a0, w.z, acc[0][2]);
            acc[0][3] = fmaf(a0, w.w, acc[0][3]);
            acc[1][0] = fmaf(a1, w.x, acc[1][0]);
            acc[1][1] = fmaf(a1, w.y, acc[1][1]);
            acc[1][2] = fmaf(a1, w.z, acc[1][2]);
            acc[1][3] = fmaf(a1, w.w, acc[1][3]);
        }
        __syncthreads();
    }

    float4 bb = *reinterpret_cast<const float4*>(b_agg + tx * 4);
    #pragma unroll
    for (int r = 0; r < 2; r++) {
        int row = m0 + ty * 2 + r;
        float4 cl = *reinterpret_cast<const float4*>(
            clone + (size_t)row * Hn + tx * 4);
        float4 o;
        o.x = cl.x + fmaxf(acc[r][0] + bb.x, 0.f);
        o.y = cl.y + fmaxf(acc[r][1] + bb.y, 0.f);
        o.z = cl.z + fmaxf(acc[r][2] + bb.z, 0.f);
        o.w = cl.w + fmaxf(acc[r][3] + bb.w, 0.f);
        *reinterpret_cast<float4*>(&out[(size_t)row * Hn + tx * 4]) = o;
    }
}

// ---------------------------------------------------------------------------
extern "C" void kernel_launch(void* const* d_in, const int* in_sizes, int n_in,
                              void* d_out, int out_size)
{
    const float* food       = (const float*)d_in[0];
    const float* thorn_rel  = (const float*)d_in[1];
    const float* clone      = (const float*)d_in[2];
    const float* clone_rel  = (const float*)d_in[3];
    const int*   thorn_mask = (const int*)  d_in[4];
    const int*   clone_mask = (const int*)  d_in[5];
    const float* W_thorn    = (const float*)d_in[6];
    // d_in[7] = b_thorn (folded into precompute)
    const float* b_thorn    = (const float*)d_in[7];
    const float* W_clone    = (const float*)d_in[8];
    const float* b_clone    = (const float*)d_in[9];
    const float* W_agg      = (const float*)d_in[10];
    const float* b_agg      = (const float*)d_in[11];
    float* out = (float*)d_out;

    precompute_kernel<<<dim3(128, 3), 256>>>(clone, W_thorn, b_thorn,
                                             W_clone, b_clone);
    branch_kernel<false><<<BC, 256>>>(thorn_rel, W_thorn + Hn * Hn, thorn_mask);
    branch_kernel<true><<<BC, 256>>>(clone_rel, W_clone + 2 * Hn * Hn, clone_mask);
    final_kernel<<<128, 256>>>(clone, food, W_agg, b_agg, out);
}